// round 16
// baseline (speedup 1.0000x reference)
#include <cuda_runtime.h>
#include <cuda_bf16.h>
#include <math.h>

#define N_NODES_MAX 100000
#define D_IN        256
#define H1          16
#define H2          32
#define KPB         128      // k per block (k-split 2)
#define KT          16       // k staged per iteration
#define G_THREADS   256
#define G_ROWS      512      // rows per block (2 per thread)
#define SXS         20       // floats per tile row (80B; LDS.128 conflict-free)
#define R_BLOCKS    1024     // reduce grid; g_part has R_BLOCKS slots

#define FMA2(d, a, b) \
    asm("fma.rn.f32x2 %0, %1, %2, %0;" : "+l"(d) : "l"(a), "l"(b))

// Scratch (device globals — BSS zero-init; every call leaves them zeroed again,
// so the kernel is deterministic across graph replays).
__device__ __align__(256) float    g_y[N_NODES_MAX * H1];  // x @ W1 fp32 (RED, k-split)
__device__ __align__(256) unsigned g_yh[N_NODES_MAX * 8];  // y in bf16 (16 bf16/row = 8 u32)
__device__ __align__(256) unsigned g_ah[N_NODES_MAX * 8];  // a accumulator in bf16x2
__device__ __align__(256) float    g_s[N_NODES_MAX];       // s[j] = sum_{e: col==j} val[e]
__device__ __align__(256) float    g_part[R_BLOCKS * H1];  // per-block partials (no atomics)

// ---------------------------------------------------------------------------
// y = x @ W1   [R11 config — best known: 41.7us]
// k-split x2, 2 rows/thread, cp.async staging, stride-20 row-major tile,
// fma.rn.f32x2, epilogue RED fp32 into g_y.
// ---------------------------------------------------------------------------
__global__ void __launch_bounds__(G_THREADS, 4)
gemm1_kernel(const float* __restrict__ x, const float* __restrict__ W1, int n) {
    extern __shared__ float smem[];
    float* sW = smem;                  // [KPB*H1] = 2048 floats (8 KB)
    float* sx = smem + KPB * H1;       // [G_ROWS][SXS] = 10240 floats (40 KB)

    int tid = threadIdx.x;
    int tile = blockIdx.x >> 1;
    int kz = blockIdx.x & 1;
    int k0 = kz * KPB;
    int row0 = tile * G_ROWS;

    reinterpret_cast<float4*>(sW)[tid] =
        reinterpret_cast<const float4*>(W1 + (size_t)k0 * H1)[tid];
    reinterpret_cast<float4*>(sW)[tid + G_THREADS] =
        reinterpret_cast<const float4*>(W1 + (size_t)k0 * H1)[tid + G_THREADS];

    unsigned long long accA[8], accB[8];   // f32x2 pairs: features (0,1)..(14,15)
#pragma unroll
    for (int j = 0; j < 8; j++) { accA[j] = 0ull; accB[j] = 0ull; }

    for (int kt = 0; kt < KPB; kt += KT) {
        __syncthreads();   // prev-iter compute done before overwriting sx
#pragma unroll
        for (int i = 0; i < 8; i++) {
            int idx = tid + i * G_THREADS;
            int r = idx >> 2, u = idx & 3;
            if (row0 + r < n) {
                unsigned int dst = (unsigned int)__cvta_generic_to_shared(
                    sx + r * SXS + u * 4);
                const float* src = x + (size_t)(row0 + r) * D_IN + k0 + kt + u * 4;
                asm volatile("cp.async.cg.shared.global [%0], [%1], 16;"
                             :: "r"(dst), "l"(src));
            }
        }
        asm volatile("cp.async.commit_group;");
        asm volatile("cp.async.wait_group 0;");
        __syncthreads();
#pragma unroll
        for (int kk4 = 0; kk4 < KT / 4; kk4++) {
            float4 xa = *reinterpret_cast<const float4*>(sx + tid * SXS + kk4 * 4);
            float4 xb = *reinterpret_cast<const float4*>(
                sx + (tid + G_THREADS) * SXS + kk4 * 4);
#pragma unroll
            for (int j = 0; j < 4; j++) {
                float fa = (j == 0) ? xa.x : (j == 1) ? xa.y : (j == 2) ? xa.z : xa.w;
                float fb = (j == 0) ? xb.x : (j == 1) ? xb.y : (j == 2) ? xb.z : xb.w;
                unsigned long long xa2, xb2;
                asm("mov.b64 %0, {%1, %1};" : "=l"(xa2) : "f"(fa));
                asm("mov.b64 %0, {%1, %1};" : "=l"(xb2) : "f"(fb));
                const ulonglong2* wp = reinterpret_cast<const ulonglong2*>(
                    sW + (kt + kk4 * 4 + j) * H1);
                ulonglong2 w01 = wp[0], w23 = wp[1], w45 = wp[2], w67 = wp[3];
                FMA2(accA[0], xa2, w01.x); FMA2(accA[1], xa2, w01.y);
                FMA2(accA[2], xa2, w23.x); FMA2(accA[3], xa2, w23.y);
                FMA2(accA[4], xa2, w45.x); FMA2(accA[5], xa2, w45.y);
                FMA2(accA[6], xa2, w67.x); FMA2(accA[7], xa2, w67.y);
                FMA2(accB[0], xb2, w01.x); FMA2(accB[1], xb2, w01.y);
                FMA2(accB[2], xb2, w23.x); FMA2(accB[3], xb2, w23.y);
                FMA2(accB[4], xb2, w45.x); FMA2(accB[5], xb2, w45.y);
                FMA2(accB[6], xb2, w67.x); FMA2(accB[7], xb2, w67.y);
            }
        }
    }
#pragma unroll
    for (int half = 0; half < 2; half++) {
        int row = row0 + tid + half * G_THREADS;
        unsigned long long* acc = half ? accB : accA;
        if (row < n) {
#pragma unroll
            for (int j = 0; j < 4; j++) {
                float f0, f1, f2, f3;
                asm("mov.b64 {%0, %1}, %2;" : "=f"(f0), "=f"(f1) : "l"(acc[2 * j]));
                asm("mov.b64 {%0, %1}, %2;" : "=f"(f2), "=f"(f3) : "l"(acc[2 * j + 1]));
                float* dst = g_y + (size_t)row * H1 + j * 4;
                asm volatile("red.global.add.v4.f32 [%0], {%1, %2, %3, %4};"
                             :: "l"(dst), "f"(f0), "f"(f1), "f"(f2), "f"(f3) : "memory");
            }
        }
    }
}

// ---------------------------------------------------------------------------
// Convert y fp32 -> bf16 (g_yh) and self-clean g_y for the next replay.
// ---------------------------------------------------------------------------
__global__ void convert_kernel(int n) {
    int i = blockIdx.x * blockDim.x + threadIdx.x;  // node*4 + q
    if (i >= n * 4) return;
    int node = i >> 2, q = i & 3;
    float4* yp = reinterpret_cast<float4*>(g_y + (size_t)node * H1 + q * 4);
    float4 v = *yp;
    *yp = make_float4(0.f, 0.f, 0.f, 0.f);          // self-clean g_y
    __nv_bfloat162 lo = __floats2bfloat162_rn(v.x, v.y);
    __nv_bfloat162 hi = __floats2bfloat162_rn(v.z, v.w);
    uint2 o;
    o.x = *reinterpret_cast<unsigned*>(&lo);
    o.y = *reinterpret_cast<unsigned*>(&hi);
    reinterpret_cast<uint2*>(g_yh)[i] = o;
}

// ---------------------------------------------------------------------------
// Edge pass, 4 edges per 4-lane group, bf16 gather + bf16x2 vector RED:
//   lane q gathers y[c][4q:4q+4] (8B) and REDs a[r][4q:4q+4] (8B bf16x2 v2)
//   s[c] += v (fp32)
// ---------------------------------------------------------------------------
__global__ void edge_kernel(const int4* __restrict__ rows4,
                            const int4* __restrict__ cols4,
                            const float4* __restrict__ vals4, int quad_count) {
    int gid = blockIdx.x * blockDim.x + threadIdx.x;
    int q = gid & 3;             // lane within group = feature quarter
    int grp = gid >> 2;          // edge-quad index
    if (grp >= quad_count) return;

    int4   r4 = __ldg(rows4 + grp);
    int4   c4 = __ldg(cols4 + grp);
    float4 v4 = __ldg(vals4 + grp);

    int   cq = (q == 0) ? c4.x : (q == 1) ? c4.y : (q == 2) ? c4.z : c4.w;
    float vq = (q == 0) ? v4.x : (q == 1) ? v4.y : (q == 2) ? v4.z : v4.w;
    atomicAdd(&g_s[cq], vq);

    int   rr[4] = {r4.x, r4.y, r4.z, r4.w};
    int   cc[4] = {c4.x, c4.y, c4.z, c4.w};
    float vv[4] = {v4.x, v4.y, v4.z, v4.w};

    uint2 yv[4];
#pragma unroll
    for (int j = 0; j < 4; j++)
        yv[j] = __ldg(reinterpret_cast<const uint2*>(g_yh) + cc[j] * 4 + q);
#pragma unroll
    for (int j = 0; j < 4; j++) {
        __nv_bfloat162 b0 = *reinterpret_cast<__nv_bfloat162*>(&yv[j].x);
        __nv_bfloat162 b1 = *reinterpret_cast<__nv_bfloat162*>(&yv[j].y);
        float2 f01 = __bfloat1622float2(b0);
        float2 f23 = __bfloat1622float2(b1);
        __nv_bfloat162 p0 = __floats2bfloat162_rn(vv[j] * f01.x, vv[j] * f01.y);
        __nv_bfloat162 p1 = __floats2bfloat162_rn(vv[j] * f23.x, vv[j] * f23.y);
        unsigned u0 = *reinterpret_cast<unsigned*>(&p0);
        unsigned u1 = *reinterpret_cast<unsigned*>(&p1);
        unsigned* dst = g_ah + (size_t)rr[j] * 8 + q * 2;
        asm volatile("red.global.add.noftz.v2.bf16x2 [%0], {%1, %2};"
                     :: "l"(dst), "r"(u0), "r"(u1) : "memory");
    }
}

// ---------------------------------------------------------------------------
// Per-block partial of t[f] = sum_i s[i]*relu(a[i][f]) into g_part[block][16]
// (plain stores — NO same-line atomics). Self-cleans g_ah/g_s.
// ---------------------------------------------------------------------------
__global__ void reduce_kernel(int n) {
    __shared__ float4 red[256];
    int tid = threadIdx.x;
    int g = tid & 3;  // feature group: covers features [4g, 4g+4)
    float4 acc = {0.f, 0.f, 0.f, 0.f};
    int total = n * 4;
    int stride = gridDim.x * blockDim.x;
    for (int idx = blockIdx.x * blockDim.x + tid; idx < total; idx += stride) {
        int i = idx >> 2;
        uint2* ap = reinterpret_cast<uint2*>(g_ah) + idx;   // node i, quad g
        uint2 av = *ap;
        float s = g_s[i];              // broadcast: all 4 lanes, same address
        if (g == 0) g_s[i] = 0.0f;     // same-warp in-order: loads precede store
        *ap = make_uint2(0u, 0u);      // self-clean g_ah
        __nv_bfloat162 b0 = *reinterpret_cast<__nv_bfloat162*>(&av.x);
        __nv_bfloat162 b1 = *reinterpret_cast<__nv_bfloat162*>(&av.y);
        float2 f01 = __bfloat1622float2(b0);
        float2 f23 = __bfloat1622float2(b1);
        acc.x += s * fmaxf(f01.x, 0.f);
        acc.y += s * fmaxf(f01.y, 0.f);
        acc.z += s * fmaxf(f23.x, 0.f);
        acc.w += s * fmaxf(f23.y, 0.f);
    }
    red[tid] = acc;
    __syncthreads();
#pragma unroll
    for (int off = 128; off >= 4; off >>= 1) {
        if (tid < off) {
            float4 o = red[tid + off];
            red[tid].x += o.x; red[tid].y += o.y; red[tid].z += o.z; red[tid].w += o.w;
        }
        __syncthreads();
    }
    if (tid < 4)   // plain STG.128: slot fully overwritten every call
        reinterpret_cast<float4*>(g_part + blockIdx.x * H1)[tid] = red[tid];
}

// ---------------------------------------------------------------------------
// Sum g_part (R_BLOCKS x 16), then out = sigmoid((t @ W2).w_out + b_out).
// ---------------------------------------------------------------------------
__global__ void final_kernel(const float* __restrict__ W2,
                             const float* __restrict__ w_out,
                             const float* __restrict__ b_out,
                             float* __restrict__ out) {
    __shared__ float sacc[256];
    __shared__ float t[H1];
    int tid = threadIdx.x;           // 256 threads
    int f = tid & 15;                // feature
    int grp = tid >> 4;              // 16 groups
    float a = 0.0f;
    for (int b = grp; b < R_BLOCKS; b += 16)   // coalesced: [b][f]
        a += g_part[b * H1 + f];
    sacc[tid] = a;
    __syncthreads();
    if (tid < 128) sacc[tid] += sacc[tid + 128];
    __syncthreads();
    if (tid < 64) sacc[tid] += sacc[tid + 64];
    __syncthreads();
    if (tid < 32) sacc[tid] += sacc[tid + 32];
    __syncthreads();
    if (tid < 16) t[tid] = sacc[tid] + sacc[tid + 16];
    __syncthreads();
    if (tid < H2) {
        float z = 0.0f;
#pragma unroll
        for (int fi = 0; fi < H1; fi++) z += t[fi] * W2[fi * H2 + tid];
        float p = z * w_out[tid];
#pragma unroll
        for (int o = 16; o > 0; o >>= 1) p += __shfl_xor_sync(0xffffffffu, p, o);
        if (tid == 0) out[0] = 1.0f / (1.0f + expf(-(p + b_out[0])));
    }
}

// ---------------------------------------------------------------------------
extern "C" void kernel_launch(void* const* d_in, const int* in_sizes, int n_in,
                              void* d_out, int out_size) {
    const float* x     = (const float*)d_in[0];
    const float* vals  = (const float*)d_in[1];
    const float* W1    = (const float*)d_in[2];
    const float* W2    = (const float*)d_in[3];
    const float* w_out = (const float*)d_in[4];
    const float* b_out = (const float*)d_in[5];
    const int*   rows  = (const int*)d_in[6];
    const int*   cols  = (const int*)d_in[7];

    int n = in_sizes[0] / D_IN;   // 100000
    int e = in_sizes[1];          // 3200000 (divisible by 4)

    int smem_bytes = (KPB * H1 + G_ROWS * SXS) * sizeof(float);  // 49152 B
    cudaFuncSetAttribute(gemm1_kernel,
                         cudaFuncAttributeMaxDynamicSharedMemorySize, smem_bytes);

    int tiles = (n + G_ROWS - 1) / G_ROWS;   // 196
    gemm1_kernel<<<tiles * 2, G_THREADS, smem_bytes>>>(x, W1, n);
    convert_kernel<<<(n * 4 + 255) / 256, 256>>>(n);
    {
        int quads = e / 4;                       // 800000
        long long work = (long long)quads * 4;
        int blocks = (int)((work + 255) / 256);
        edge_kernel<<<blocks, 256>>>((const int4*)rows, (const int4*)cols,
                                     (const float4*)vals, quads);
    }
    reduce_kernel<<<R_BLOCKS, 256>>>(n);
    final_kernel<<<1, 256>>>(W2, w_out, b_out, (float*)d_out);
}

// round 17
// speedup vs baseline: 1.0408x; 1.0408x over previous
#include <cuda_runtime.h>
#include <cuda_bf16.h>
#include <math.h>

#define N_NODES_MAX 100000
#define D_IN        256
#define H1          16
#define H2          32
#define KPB         128      // k per block (k-split 2)
#define KT          16       // k staged per iteration
#define G_THREADS   256
#define G_ROWS      512      // rows per block (2 per thread)
#define SXS         20       // floats per tile row (80B; LDS.128 conflict-free)
#define R_BLOCKS    512      // reduce grid; g_part has R_BLOCKS slots

#define FMA2(d, a, b) \
    asm("fma.rn.f32x2 %0, %1, %2, %0;" : "+l"(d) : "l"(a), "l"(b))

// Scratch (device globals — BSS zero-init. Cleaning protocol: convert_kernel
// zeroes g_y/g_ah/g_s each call BEFORE edge_kernel refills them, so every
// call sees the same state -> deterministic across graph replays).
__device__ __align__(256) float    g_y[N_NODES_MAX * H1];  // x @ W1 fp32 (RED, k-split)
__device__ __align__(256) unsigned g_yh[N_NODES_MAX * 8];  // y in bf16 (16 bf16/row = 8 u32)
__device__ __align__(256) unsigned g_ah[N_NODES_MAX * 8];  // a accumulator in bf16x2
__device__ __align__(256) float    g_s[N_NODES_MAX];       // s[j] = sum_{e: col==j} val[e]
__device__ __align__(256) float    g_part[R_BLOCKS * H1];  // per-block partials (no atomics)

// ---------------------------------------------------------------------------
// y = x @ W1   [R11 config — best known: 41.7us]
// k-split x2, 2 rows/thread, cp.async staging, stride-20 row-major tile,
// fma.rn.f32x2, epilogue RED fp32 into g_y.
// ---------------------------------------------------------------------------
__global__ void __launch_bounds__(G_THREADS, 4)
gemm1_kernel(const float* __restrict__ x, const float* __restrict__ W1, int n) {
    extern __shared__ float smem[];
    float* sW = smem;                  // [KPB*H1] = 2048 floats (8 KB)
    float* sx = smem + KPB * H1;       // [G_ROWS][SXS] = 10240 floats (40 KB)

    int tid = threadIdx.x;
    int tile = blockIdx.x >> 1;
    int kz = blockIdx.x & 1;
    int k0 = kz * KPB;
    int row0 = tile * G_ROWS;

    reinterpret_cast<float4*>(sW)[tid] =
        reinterpret_cast<const float4*>(W1 + (size_t)k0 * H1)[tid];
    reinterpret_cast<float4*>(sW)[tid + G_THREADS] =
        reinterpret_cast<const float4*>(W1 + (size_t)k0 * H1)[tid + G_THREADS];

    unsigned long long accA[8], accB[8];   // f32x2 pairs: features (0,1)..(14,15)
#pragma unroll
    for (int j = 0; j < 8; j++) { accA[j] = 0ull; accB[j] = 0ull; }

    for (int kt = 0; kt < KPB; kt += KT) {
        __syncthreads();   // prev-iter compute done before overwriting sx
#pragma unroll
        for (int i = 0; i < 8; i++) {
            int idx = tid + i * G_THREADS;
            int r = idx >> 2, u = idx & 3;
            if (row0 + r < n) {
                unsigned int dst = (unsigned int)__cvta_generic_to_shared(
                    sx + r * SXS + u * 4);
                const float* src = x + (size_t)(row0 + r) * D_IN + k0 + kt + u * 4;
                asm volatile("cp.async.cg.shared.global [%0], [%1], 16;"
                             :: "r"(dst), "l"(src));
            }
        }
        asm volatile("cp.async.commit_group;");
        asm volatile("cp.async.wait_group 0;");
        __syncthreads();
#pragma unroll
        for (int kk4 = 0; kk4 < KT / 4; kk4++) {
            float4 xa = *reinterpret_cast<const float4*>(sx + tid * SXS + kk4 * 4);
            float4 xb = *reinterpret_cast<const float4*>(
                sx + (tid + G_THREADS) * SXS + kk4 * 4);
#pragma unroll
            for (int j = 0; j < 4; j++) {
                float fa = (j == 0) ? xa.x : (j == 1) ? xa.y : (j == 2) ? xa.z : xa.w;
                float fb = (j == 0) ? xb.x : (j == 1) ? xb.y : (j == 2) ? xb.z : xb.w;
                unsigned long long xa2, xb2;
                asm("mov.b64 %0, {%1, %1};" : "=l"(xa2) : "f"(fa));
                asm("mov.b64 %0, {%1, %1};" : "=l"(xb2) : "f"(fb));
                const ulonglong2* wp = reinterpret_cast<const ulonglong2*>(
                    sW + (kt + kk4 * 4 + j) * H1);
                ulonglong2 w01 = wp[0], w23 = wp[1], w45 = wp[2], w67 = wp[3];
                FMA2(accA[0], xa2, w01.x); FMA2(accA[1], xa2, w01.y);
                FMA2(accA[2], xa2, w23.x); FMA2(accA[3], xa2, w23.y);
                FMA2(accA[4], xa2, w45.x); FMA2(accA[5], xa2, w45.y);
                FMA2(accA[6], xa2, w67.x); FMA2(accA[7], xa2, w67.y);
                FMA2(accB[0], xb2, w01.x); FMA2(accB[1], xb2, w01.y);
                FMA2(accB[2], xb2, w23.x); FMA2(accB[3], xb2, w23.y);
                FMA2(accB[4], xb2, w45.x); FMA2(accB[5], xb2, w45.y);
                FMA2(accB[6], xb2, w67.x); FMA2(accB[7], xb2, w67.y);
            }
        }
    }
#pragma unroll
    for (int half = 0; half < 2; half++) {
        int row = row0 + tid + half * G_THREADS;
        unsigned long long* acc = half ? accB : accA;
        if (row < n) {
#pragma unroll
            for (int j = 0; j < 4; j++) {
                float f0, f1, f2, f3;
                asm("mov.b64 {%0, %1}, %2;" : "=f"(f0), "=f"(f1) : "l"(acc[2 * j]));
                asm("mov.b64 {%0, %1}, %2;" : "=f"(f2), "=f"(f3) : "l"(acc[2 * j + 1]));
                float* dst = g_y + (size_t)row * H1 + j * 4;
                asm volatile("red.global.add.v4.f32 [%0], {%1, %2, %3, %4};"
                             :: "l"(dst), "f"(f0), "f"(f1), "f"(f2), "f"(f3) : "memory");
            }
        }
    }
}

// ---------------------------------------------------------------------------
// Convert y fp32 -> bf16 (g_yh). Owns ALL scratch cleaning for this call:
// zeroes g_y (for next call's gemm1 RED), g_ah and g_s (refilled by this
// call's edge_kernel below). reduce_kernel is then pure-read.
// ---------------------------------------------------------------------------
__global__ void convert_kernel(int n) {
    int i = blockIdx.x * blockDim.x + threadIdx.x;  // node*4 + q
    if (i >= n * 4) return;
    int node = i >> 2, q = i & 3;
    float4* yp = reinterpret_cast<float4*>(g_y + (size_t)node * H1 + q * 4);
    float4 v = *yp;
    *yp = make_float4(0.f, 0.f, 0.f, 0.f);          // clean g_y
    __nv_bfloat162 lo = __floats2bfloat162_rn(v.x, v.y);
    __nv_bfloat162 hi = __floats2bfloat162_rn(v.z, v.w);
    uint2 o;
    o.x = *reinterpret_cast<unsigned*>(&lo);
    o.y = *reinterpret_cast<unsigned*>(&hi);
    reinterpret_cast<uint2*>(g_yh)[i] = o;
    reinterpret_cast<uint2*>(g_ah)[i] = make_uint2(0u, 0u);  // clean g_ah
    if (q == 0) g_s[node] = 0.0f;                            // clean g_s
}

// ---------------------------------------------------------------------------
// Edge pass, 4 edges per 4-lane group, bf16 gather + bf16x2 vector RED:
//   lane q gathers y[c][4q:4q+4] (8B) and REDs a[r][4q:4q+4] (8B bf16x2 v2)
//   s[c] += v (fp32)
// ---------------------------------------------------------------------------
__global__ void edge_kernel(const int4* __restrict__ rows4,
                            const int4* __restrict__ cols4,
                            const float4* __restrict__ vals4, int quad_count) {
    int gid = blockIdx.x * blockDim.x + threadIdx.x;
    int q = gid & 3;             // lane within group = feature quarter
    int grp = gid >> 2;          // edge-quad index
    if (grp >= quad_count) return;

    int4   r4 = __ldg(rows4 + grp);
    int4   c4 = __ldg(cols4 + grp);
    float4 v4 = __ldg(vals4 + grp);

    int   cq = (q == 0) ? c4.x : (q == 1) ? c4.y : (q == 2) ? c4.z : c4.w;
    float vq = (q == 0) ? v4.x : (q == 1) ? v4.y : (q == 2) ? v4.z : v4.w;
    atomicAdd(&g_s[cq], vq);

    int   rr[4] = {r4.x, r4.y, r4.z, r4.w};
    int   cc[4] = {c4.x, c4.y, c4.z, c4.w};
    float vv[4] = {v4.x, v4.y, v4.z, v4.w};

    uint2 yv[4];
#pragma unroll
    for (int j = 0; j < 4; j++)
        yv[j] = __ldg(reinterpret_cast<const uint2*>(g_yh) + cc[j] * 4 + q);
#pragma unroll
    for (int j = 0; j < 4; j++) {
        __nv_bfloat162 b0 = *reinterpret_cast<__nv_bfloat162*>(&yv[j].x);
        __nv_bfloat162 b1 = *reinterpret_cast<__nv_bfloat162*>(&yv[j].y);
        float2 f01 = __bfloat1622float2(b0);
        float2 f23 = __bfloat1622float2(b1);
        __nv_bfloat162 p0 = __floats2bfloat162_rn(vv[j] * f01.x, vv[j] * f01.y);
        __nv_bfloat162 p1 = __floats2bfloat162_rn(vv[j] * f23.x, vv[j] * f23.y);
        unsigned u0 = *reinterpret_cast<unsigned*>(&p0);
        unsigned u1 = *reinterpret_cast<unsigned*>(&p1);
        unsigned* dst = g_ah + (size_t)rr[j] * 8 + q * 2;
        asm volatile("red.global.add.noftz.v2.bf16x2 [%0], {%1, %2};"
                     :: "l"(dst), "r"(u0), "r"(u1) : "memory");
    }
}

// ---------------------------------------------------------------------------
// Per-block partial of t[f] = sum_i s[i]*relu(a[i][f]) into g_part[block][16].
// PURE READ (uint4 = half a node row per thread); no cleanup stores here.
// ---------------------------------------------------------------------------
__global__ void reduce_kernel(int n) {
    __shared__ float4 red[256];
    int tid = threadIdx.x;
    int h = tid & 1;  // half of the 16-wide feature row: features [8h, 8h+8)
    float4 acc0 = {0.f, 0.f, 0.f, 0.f};
    float4 acc1 = {0.f, 0.f, 0.f, 0.f};
    int total = n * 2;
    int stride = gridDim.x * blockDim.x;
    for (int idx = blockIdx.x * blockDim.x + tid; idx < total; idx += stride) {
        int i = idx >> 1;
        uint4 av = __ldg(reinterpret_cast<const uint4*>(g_ah) + idx);
        float s = __ldg(g_s + i);      // 2 lanes same address: 1 sector
        __nv_bfloat162 b0 = *reinterpret_cast<__nv_bfloat162*>(&av.x);
        __nv_bfloat162 b1 = *reinterpret_cast<__nv_bfloat162*>(&av.y);
        __nv_bfloat162 b2 = *reinterpret_cast<__nv_bfloat162*>(&av.z);
        __nv_bfloat162 b3 = *reinterpret_cast<__nv_bfloat162*>(&av.w);
        float2 f0 = __bfloat1622float2(b0);
        float2 f1 = __bfloat1622float2(b1);
        float2 f2 = __bfloat1622float2(b2);
        float2 f3 = __bfloat1622float2(b3);
        acc0.x += s * fmaxf(f0.x, 0.f);
        acc0.y += s * fmaxf(f0.y, 0.f);
        acc0.z += s * fmaxf(f1.x, 0.f);
        acc0.w += s * fmaxf(f1.y, 0.f);
        acc1.x += s * fmaxf(f2.x, 0.f);
        acc1.y += s * fmaxf(f2.y, 0.f);
        acc1.z += s * fmaxf(f3.x, 0.f);
        acc1.w += s * fmaxf(f3.y, 0.f);
    }
    // Warp-level: fold the h=1 half into lanes with h=0, then tree over smem.
    // Layout red[tid]: thread handles features [8h..8h+8) via acc0(4)+acc1(4).
    // Store both halves: use two smem banks of float4 per thread pair.
    __shared__ float4 redB[256];
    red[tid] = acc0;
    redB[tid] = acc1;
    __syncthreads();
#pragma unroll
    for (int off = 128; off >= 2; off >>= 1) {
        if (tid < off) {
            float4 o = red[tid + off], p = redB[tid + off];
            red[tid].x += o.x; red[tid].y += o.y; red[tid].z += o.z; red[tid].w += o.w;
            redB[tid].x += p.x; redB[tid].y += p.y; redB[tid].z += p.z; redB[tid].w += p.w;
        }
        __syncthreads();
    }
    // red[0]/redB[0] = features 0-3 / 4-7 ; red[1]/redB[1] = features 8-11 / 12-15
    if (tid < 4) {
        float4 out4;
        if (tid == 0) out4 = red[0];
        else if (tid == 1) out4 = redB[0];
        else if (tid == 2) out4 = red[1];
        else out4 = redB[1];
        reinterpret_cast<float4*>(g_part + blockIdx.x * H1)[tid] = out4;
    }
}

// ---------------------------------------------------------------------------
// Sum g_part (R_BLOCKS x 16), then out = sigmoid((t @ W2).w_out + b_out).
// ---------------------------------------------------------------------------
__global__ void final_kernel(const float* __restrict__ W2,
                             const float* __restrict__ w_out,
                             const float* __restrict__ b_out,
                             float* __restrict__ out) {
    __shared__ float sacc[256];
    __shared__ float t[H1];
    int tid = threadIdx.x;           // 256 threads
    int f = tid & 15;                // feature
    int grp = tid >> 4;              // 16 groups
    float a = 0.0f;
    for (int b = grp; b < R_BLOCKS; b += 16)   // coalesced: [b][f]
        a += g_part[b * H1 + f];
    sacc[tid] = a;
    __syncthreads();
    if (tid < 128) sacc[tid] += sacc[tid + 128];
    __syncthreads();
    if (tid < 64) sacc[tid] += sacc[tid + 64];
    __syncthreads();
    if (tid < 32) sacc[tid] += sacc[tid + 32];
    __syncthreads();
    if (tid < 16) t[tid] = sacc[tid] + sacc[tid + 16];
    __syncthreads();
    if (tid < H2) {
        float z = 0.0f;
#pragma unroll
        for (int fi = 0; fi < H1; fi++) z += t[fi] * W2[fi * H2 + tid];
        float p = z * w_out[tid];
#pragma unroll
        for (int o = 16; o > 0; o >>= 1) p += __shfl_xor_sync(0xffffffffu, p, o);
        if (tid == 0) out[0] = 1.0f / (1.0f + expf(-(p + b_out[0])));
    }
}

// ---------------------------------------------------------------------------
extern "C" void kernel_launch(void* const* d_in, const int* in_sizes, int n_in,
                              void* d_out, int out_size) {
    const float* x     = (const float*)d_in[0];
    const float* vals  = (const float*)d_in[1];
    const float* W1    = (const float*)d_in[2];
    const float* W2    = (const float*)d_in[3];
    const float* w_out = (const float*)d_in[4];
    const float* b_out = (const float*)d_in[5];
    const int*   rows  = (const int*)d_in[6];
    const int*   cols  = (const int*)d_in[7];

    int n = in_sizes[0] / D_IN;   // 100000
    int e = in_sizes[1];          // 3200000 (divisible by 4)

    int smem_bytes = (KPB * H1 + G_ROWS * SXS) * sizeof(float);  // 49152 B
    cudaFuncSetAttribute(gemm1_kernel,
                         cudaFuncAttributeMaxDynamicSharedMemorySize, smem_bytes);

    int tiles = (n + G_ROWS - 1) / G_ROWS;   // 196
    gemm1_kernel<<<tiles * 2, G_THREADS, smem_bytes>>>(x, W1, n);
    convert_kernel<<<(n * 4 + 255) / 256, 256>>>(n);
    {
        int quads = e / 4;                       // 800000
        long long work = (long long)quads * 4;
        int blocks = (int)((work + 255) / 256);
        edge_kernel<<<blocks, 256>>>((const int4*)rows, (const int4*)cols,
                                     (const float4*)vals, quads);
    }
    reduce_kernel<<<R_BLOCKS, 256>>>(n);
    final_kernel<<<1, 256>>>(W2, w_out, b_out, (float*)d_out);
}